// round 2
// baseline (speedup 1.0000x reference)
#include <cuda_runtime.h>

#define DD 64
#define EPW 8            // edges per warp per tile
#define WARPS 8          // warps per block
#define TILE_E (EPW * WARPS)   // 64 edges per block-tile
#define SMEM_FLOATS (16384 + WARPS * EPW * 128)   // W1(8192)+W2(4096)+Wg(4096)+PE
#define SMEM_BYTES (SMEM_FLOATS * 4)
#define MAXE (1 << 20)
#define MAXN 65536

// scratch device globals (no allocation allowed)
__device__ int g_cnt[MAXN];
__device__ int g_src[MAXE];
__device__ int g_dst[MAXE];
__device__ int g_is64;

__global__ void zero_kernel(float* __restrict__ out, int n_out, int n_cnt) {
    int stride = gridDim.x * blockDim.x;
    int i = blockIdx.x * blockDim.x + threadIdx.x;
    for (int j = i; j < n_out; j += stride) out[j] = 0.0f;
    for (int j = i; j < n_cnt; j += stride) g_cnt[j] = 0;
}

// Detect int64 vs int32 edge_index: int64 little-endian -> all odd int32 words
// are high halves == 0 (indices are nonneg < 2^31). For int32 data (random
// indices), 64 consecutive odd words all zero is statistically impossible.
__global__ void detect_kernel(const int* __restrict__ w) {
    if (threadIdx.x == 0) {
        int all_zero = 1;
        for (int i = 0; i < 64; i++)
            if (w[2 * i + 1] != 0) { all_zero = 0; break; }
        g_is64 = all_zero;
    }
}

// Expand edge_index into int32 src/dst (clamped) + per-src-node edge counts.
__global__ void decode_kernel(const void* __restrict__ buf, int E, int N) {
    int i = blockIdx.x * blockDim.x + threadIdx.x;
    if (i >= E) return;
    int s, d;
    if (g_is64) {
        const long long* p = (const long long*)buf;
        s = (int)p[i];
        d = (int)p[E + i];
    } else {
        const int* p = (const int*)buf;
        s = p[i];
        d = p[E + i];
    }
    s = min(max(s, 0), N - 1);
    d = min(max(d, 0), N - 1);
    g_src[i] = s;
    g_dst[i] = d;
    atomicAdd(&g_cnt[s], 1);
}

__global__ __launch_bounds__(256, 2) void fused_edge_kernel(
    const float* __restrict__ node_emb,
    const float* __restrict__ W1, const float* __restrict__ b1,
    const float* __restrict__ W2, const float* __restrict__ b2,
    const float* __restrict__ Wg, const float* __restrict__ bg,
    float* __restrict__ out, int E)
{
    extern __shared__ float smem[];
    float* sW1 = smem;            // [128][64]
    float* sW2 = smem + 8192;     // [64][64]
    float* sWg = smem + 12288;    // [64][64]

    int tid = threadIdx.x;
    for (int i = tid; i < 8192; i += blockDim.x) sW1[i] = W1[i];
    for (int i = tid; i < 4096; i += blockDim.x) { sW2[i] = W2[i]; sWg[i] = Wg[i]; }
    __syncthreads();

    const int warp = tid >> 5;
    const int l    = tid & 31;
    float* sPE = smem + 16384 + warp * (EPW * 128);   // per-warp staging [8][128]

    const float b1a = b1[l], b1b = b1[l + 32];
    const float b2a = b2[l], b2b = b2[l + 32];
    const float bga = bg[l], bgb = bg[l + 32];

    const int ntiles = (E + TILE_E - 1) / TILE_E;
    for (int tile = blockIdx.x; tile < ntiles; tile += gridDim.x) {
        const int ebase  = tile * TILE_E + warp * EPW;
        const int nvalid = min(EPW, E - ebase);
        if (nvalid <= 0) continue;   // no block-level sync inside loop, safe

        // ---- gather pair embeddings: lanes 0-15 load src row, 16-31 dst row ----
        int sidx[EPW];
        #pragma unroll
        for (int e = 0; e < EPW; e++) {
            int ei = ebase + ((e < nvalid) ? e : (nvalid - 1));  // clamp (dupes unscattered)
            int s = g_src[ei];
            int d = g_dst[ei];
            sidx[e] = s;
            const float4* row = (const float4*)(node_emb + (long long)(l < 16 ? s : d) * DD);
            int li = l & 15;
            ((float4*)(sPE + e * 128 + (l < 16 ? 0 : 64)))[li] = row[li];
        }
        __syncwarp();

        // ---- layer 1: h = relu(pe @ W1 + b1), lane owns cols {l, l+32} ----
        float a0[EPW], a1[EPW];
        #pragma unroll
        for (int e = 0; e < EPW; e++) { a0[e] = b1a; a1[e] = b1b; }
        #pragma unroll 2
        for (int k = 0; k < 128; k++) {
            float w0 = sW1[k * 64 + l];
            float w1 = sW1[k * 64 + 32 + l];
            #pragma unroll
            for (int e = 0; e < EPW; e++) {
                float p = sPE[e * 128 + k];
                a0[e] = fmaf(p, w0, a0[e]);
                a1[e] = fmaf(p, w1, a1[e]);
            }
        }
        __syncwarp();
        #pragma unroll
        for (int e = 0; e < EPW; e++) {
            sPE[e * 128 + l]      = fmaxf(a0[e], 0.0f);
            sPE[e * 128 + 32 + l] = fmaxf(a1[e], 0.0f);
        }
        __syncwarp();

        // ---- layer 2: interaction = h @ W2 + b2 ----
        float t0[EPW], t1[EPW];
        #pragma unroll
        for (int e = 0; e < EPW; e++) { t0[e] = b2a; t1[e] = b2b; }
        #pragma unroll 2
        for (int k = 0; k < 64; k++) {
            float w0 = sW2[k * 64 + l];
            float w1 = sW2[k * 64 + 32 + l];
            #pragma unroll
            for (int e = 0; e < EPW; e++) {
                float p = sPE[e * 128 + k];
                t0[e] = fmaf(p, w0, t0[e]);
                t1[e] = fmaf(p, w1, t1[e]);
            }
        }
        __syncwarp();
        #pragma unroll
        for (int e = 0; e < EPW; e++) {
            sPE[e * 128 + 64 + l] = t0[e];
            sPE[e * 128 + 96 + l] = t1[e];
        }
        __syncwarp();

        // ---- gate: g = interaction @ Wg + bg ----
        float g0[EPW], g1[EPW];
        #pragma unroll
        for (int e = 0; e < EPW; e++) { g0[e] = bga; g1[e] = bgb; }
        #pragma unroll 2
        for (int k = 0; k < 64; k++) {
            float w0 = sWg[k * 64 + l];
            float w1 = sWg[k * 64 + 32 + l];
            #pragma unroll
            for (int e = 0; e < EPW; e++) {
                float p = sPE[e * 128 + 64 + k];
                g0[e] = fmaf(p, w0, g0[e]);
                g1[e] = fmaf(p, w1, g1[e]);
            }
        }

        // ---- sigmoid gate, elementwise product, scatter-add to src rows ----
        #pragma unroll
        for (int e = 0; e < EPW; e++) {
            if (e < nvalid) {
                float ga = 1.0f / (1.0f + __expf(-g0[e]));
                float gb = 1.0f / (1.0f + __expf(-g1[e]));
                float* orow = out + (long long)sidx[e] * DD;
                atomicAdd(orow + l,      t0[e] * ga);
                atomicAdd(orow + 32 + l, t1[e] * gb);
            }
        }
    }
}

__global__ void norm_kernel(float* __restrict__ out, int n_out) {
    int i = blockIdx.x * blockDim.x + threadIdx.x;
    if (i < n_out) {
        float c = (float)g_cnt[i >> 6];
        out[i] = out[i] / fmaxf(c, 1.0f);
    }
}

extern "C" void kernel_launch(void* const* d_in, const int* in_sizes, int n_in,
                              void* d_out, int out_size)
{
    const float* node_emb = (const float*)d_in[0];
    const void*  ei       = d_in[1];
    const float* W1       = (const float*)d_in[2];
    const float* b1       = (const float*)d_in[3];
    const float* W2       = (const float*)d_in[4];
    const float* b2       = (const float*)d_in[5];
    const float* Wg       = (const float*)d_in[6];
    const float* bg       = (const float*)d_in[7];
    float*       out      = (float*)d_out;

    const int N = in_sizes[0] / DD;
    const int E = in_sizes[1] / 2;

    zero_kernel<<<256, 256>>>(out, N * DD, N);
    detect_kernel<<<1, 32>>>((const int*)ei);
    decode_kernel<<<(E + 255) / 256, 256>>>(ei, E, N);

    cudaFuncSetAttribute(fused_edge_kernel,
                         cudaFuncAttributeMaxDynamicSharedMemorySize, SMEM_BYTES);
    fused_edge_kernel<<<296, 256, SMEM_BYTES>>>(node_emb,
                                                W1, b1, W2, b2, Wg, bg, out, E);

    norm_kernel<<<(N * DD + 255) / 256, 256>>>(out, N * DD);
}

// round 5
// speedup vs baseline: 1.2890x; 1.2890x over previous
#include <cuda_runtime.h>

#define DD 64
#define EPW 8            // edges per warp per tile
#define WARPS 8          // warps per block
#define TILE_E (EPW * WARPS)   // 64 edges per block-tile

// smem layout (floats):
//  sW1t: [64][132]  transposed W1, padded   -> 8448
//  sW2t: [64][68]   transposed W2, padded   -> 4352
//  sWgt: [64][68]   transposed Wg, padded   -> 4352
//  sPE : per-warp [8][128] staging          -> 8192
#define W1T_OFF 0
#define W2T_OFF 8448
#define WGT_OFF 12800
#define PE_OFF  17152
#define SMEM_FLOATS (PE_OFF + WARPS * EPW * 128)
#define SMEM_BYTES (SMEM_FLOATS * 4)

#define MAXE (1 << 20)
#define MAXN 65536

// scratch device globals (no allocation allowed)
__device__ int g_cnt[MAXN];
__device__ int g_src[MAXE];
__device__ int g_dst[MAXE];
__device__ int g_is64;

// packed dual-fp32 FMA (sm_10x FFMA2): acc.{lo,hi} += p.{lo,hi} * w.{lo,hi}
__device__ __forceinline__ void ffma2(unsigned long long& acc,
                                      unsigned long long p,
                                      unsigned long long w) {
    asm("fma.rn.f32x2 %0, %1, %2, %0;" : "+l"(acc) : "l"(p), "l"(w));
}
__device__ __forceinline__ float f2lo(unsigned long long v) {
    return __uint_as_float((unsigned)v);
}
__device__ __forceinline__ float f2hi(unsigned long long v) {
    return __uint_as_float((unsigned)(v >> 32));
}

__global__ void zero_kernel(float* __restrict__ out, int n_out, int n_cnt) {
    int stride = gridDim.x * blockDim.x;
    int i = blockIdx.x * blockDim.x + threadIdx.x;
    for (int j = i; j < n_out; j += stride) out[j] = 0.0f;
    for (int j = i; j < n_cnt; j += stride) g_cnt[j] = 0;
}

// Detect int64 vs int32 edge_index: int64 little-endian -> all odd int32 words
// (high halves, indices < 2^31) are zero. Impossible for random int32 indices.
__global__ void detect_kernel(const int* __restrict__ w) {
    if (threadIdx.x == 0) {
        int all_zero = 1;
        for (int i = 0; i < 64; i++)
            if (w[2 * i + 1] != 0) { all_zero = 0; break; }
        g_is64 = all_zero;
    }
}

// Expand edge_index into int32 src/dst (clamped) + per-src-node edge counts.
__global__ void decode_kernel(const void* __restrict__ buf, int E, int N) {
    int i = blockIdx.x * blockDim.x + threadIdx.x;
    if (i >= E) return;
    int s, d;
    if (g_is64) {
        const long long* p = (const long long*)buf;
        s = (int)p[i];
        d = (int)p[E + i];
    } else {
        const int* p = (const int*)buf;
        s = p[i];
        d = p[E + i];
    }
    s = min(max(s, 0), N - 1);
    d = min(max(d, 0), N - 1);
    g_src[i] = s;
    g_dst[i] = d;
    atomicAdd(&g_cnt[s], 1);
}

__global__ __launch_bounds__(256, 2) void fused_edge_kernel(
    const float* __restrict__ node_emb,
    const float* __restrict__ W1, const float* __restrict__ b1,
    const float* __restrict__ W2, const float* __restrict__ b2,
    const float* __restrict__ Wg, const float* __restrict__ bg,
    float* __restrict__ out, int E)
{
    extern __shared__ float smem[];
    float* sW1t = smem + W1T_OFF;   // [col][k] stride 132
    float* sW2t = smem + W2T_OFF;   // [col][k] stride 68
    float* sWgt = smem + WGT_OFF;   // [col][k] stride 68

    int tid = threadIdx.x;
    // transpose weights into smem: sWt[col*stride + k] = W[k*64 + col]
    for (int i = tid; i < 64 * 128; i += blockDim.x) {
        int c = i >> 7, k = i & 127;
        sW1t[c * 132 + k] = W1[k * 64 + c];
    }
    for (int i = tid; i < 64 * 64; i += blockDim.x) {
        int c = i >> 6, k = i & 63;
        sW2t[c * 68 + k] = W2[k * 64 + c];
        sWgt[c * 68 + k] = Wg[k * 64 + c];
    }
    __syncthreads();

    const int warp = tid >> 5;
    const int l    = tid & 31;
    float* sPE = smem + PE_OFF + warp * (EPW * 128);   // per-warp staging [8][128]

    const float b1a = b1[l], b1b = b1[l + 32];
    const float b2a = b2[l], b2b = b2[l + 32];
    const float bga = bg[l], bgb = bg[l + 32];

    const int ntiles = (E + TILE_E - 1) / TILE_E;
    for (int tile = blockIdx.x; tile < ntiles; tile += gridDim.x) {
        const int ebase  = tile * TILE_E + warp * EPW;
        const int nvalid = min(EPW, E - ebase);
        if (nvalid <= 0) continue;   // no block-level sync inside loop, safe

        // ---- gather pair embeddings: lanes 0-15 load src row, 16-31 dst row ----
        int sidx[EPW];
        #pragma unroll
        for (int e = 0; e < EPW; e++) {
            int ei = ebase + ((e < nvalid) ? e : (nvalid - 1));  // clamp (dupes unscattered)
            int s = g_src[ei];
            int d = g_dst[ei];
            sidx[e] = s;
            const float4* row = (const float4*)(node_emb + (long long)(l < 16 ? s : d) * DD);
            int li = l & 15;
            ((float4*)(sPE + e * 128 + (l < 16 ? 0 : 64)))[li] = row[li];
        }
        __syncwarp();

        // ---- layer 1: h = relu(pe @ W1 + b1), lane owns cols {l, l+32} ----
        {
            unsigned long long A0[EPW], A1[EPW];
            #pragma unroll
            for (int e = 0; e < EPW; e++) { A0[e] = 0ULL; A1[e] = 0ULL; }
            #pragma unroll 4
            for (int k4 = 0; k4 < 128; k4 += 4) {
                ulonglong2 w0 = *(const ulonglong2*)(sW1t + l * 132 + k4);
                ulonglong2 w1 = *(const ulonglong2*)(sW1t + (l + 32) * 132 + k4);
                #pragma unroll
                for (int e = 0; e < EPW; e++) {
                    ulonglong2 p = *(const ulonglong2*)(sPE + e * 128 + k4);
                    ffma2(A0[e], p.x, w0.x); ffma2(A0[e], p.y, w0.y);
                    ffma2(A1[e], p.x, w1.x); ffma2(A1[e], p.y, w1.y);
                }
            }
            __syncwarp();
            #pragma unroll
            for (int e = 0; e < EPW; e++) {
                sPE[e * 128 + l]      = fmaxf(f2lo(A0[e]) + f2hi(A0[e]) + b1a, 0.0f);
                sPE[e * 128 + 32 + l] = fmaxf(f2lo(A1[e]) + f2hi(A1[e]) + b1b, 0.0f);
            }
            __syncwarp();
        }

        // ---- layer 2: interaction = h @ W2 + b2 ----
        float t0[EPW], t1[EPW];
        {
            unsigned long long A0[EPW], A1[EPW];
            #pragma unroll
            for (int e = 0; e < EPW; e++) { A0[e] = 0ULL; A1[e] = 0ULL; }
            #pragma unroll 4
            for (int k4 = 0; k4 < 64; k4 += 4) {
                ulonglong2 w0 = *(const ulonglong2*)(sW2t + l * 68 + k4);
                ulonglong2 w1 = *(const ulonglong2*)(sW2t + (l + 32) * 68 + k4);
                #pragma unroll
                for (int e = 0; e < EPW; e++) {
                    ulonglong2 p = *(const ulonglong2*)(sPE + e * 128 + k4);
                    ffma2(A0[e], p.x, w0.x); ffma2(A0[e], p.y, w0.y);
                    ffma2(A1[e], p.x, w1.x); ffma2(A1[e], p.y, w1.y);
                }
            }
            __syncwarp();
            #pragma unroll
            for (int e = 0; e < EPW; e++) {
                t0[e] = f2lo(A0[e]) + f2hi(A0[e]) + b2a;
                t1[e] = f2lo(A1[e]) + f2hi(A1[e]) + b2b;
                sPE[e * 128 + 64 + l] = t0[e];
                sPE[e * 128 + 96 + l] = t1[e];
            }
            __syncwarp();
        }

        // ---- gate: g = sigmoid(interaction @ Wg + bg); scatter t*g ----
        {
            unsigned long long A0[EPW], A1[EPW];
            #pragma unroll
            for (int e = 0; e < EPW; e++) { A0[e] = 0ULL; A1[e] = 0ULL; }
            #pragma unroll 4
            for (int k4 = 0; k4 < 64; k4 += 4) {
                ulonglong2 w0 = *(const ulonglong2*)(sWgt + l * 68 + k4);
                ulonglong2 w1 = *(const ulonglong2*)(sWgt + (l + 32) * 68 + k4);
                #pragma unroll
                for (int e = 0; e < EPW; e++) {
                    ulonglong2 p = *(const ulonglong2*)(sPE + e * 128 + 64 + k4);
                    ffma2(A0[e], p.x, w0.x); ffma2(A0[e], p.y, w0.y);
                    ffma2(A1[e], p.x, w1.x); ffma2(A1[e], p.y, w1.y);
                }
            }
            #pragma unroll
            for (int e = 0; e < EPW; e++) {
                if (e < nvalid) {
                    float ga = f2lo(A0[e]) + f2hi(A0[e]) + bga;
                    float gb = f2lo(A1[e]) + f2hi(A1[e]) + bgb;
                    ga = 1.0f / (1.0f + __expf(-ga));
                    gb = 1.0f / (1.0f + __expf(-gb));
                    float* orow = out + (long long)sidx[e] * DD;
                    atomicAdd(orow + l,      t0[e] * ga);
                    atomicAdd(orow + 32 + l, t1[e] * gb);
                }
            }
        }
    }
}

__global__ void norm_kernel(float* __restrict__ out, int n_out) {
    int i = blockIdx.x * blockDim.x + threadIdx.x;
    if (i < n_out) {
        float c = (float)g_cnt[i >> 6];
        out[i] = out[i] / fmaxf(c, 1.0f);
    }
}

extern "C" void kernel_launch(void* const* d_in, const int* in_sizes, int n_in,
                              void* d_out, int out_size)
{
    const float* node_emb = (const float*)d_in[0];
    const void*  ei       = d_in[1];
    const float* W1       = (const float*)d_in[2];
    const float* b1       = (const float*)d_in[3];
    const float* W2       = (const float*)d_in[4];
    const float* b2       = (const float*)d_in[5];
    const float* Wg       = (const float*)d_in[6];
    const float* bg       = (const float*)d_in[7];
    float*       out      = (float*)d_out;

    const int N = in_sizes[0] / DD;
    const int E = in_sizes[1] / 2;

    zero_kernel<<<256, 256>>>(out, N * DD, N);
    detect_kernel<<<1, 32>>>((const int*)ei);
    decode_kernel<<<(E + 255) / 256, 256>>>(ei, E, N);

    cudaFuncSetAttribute(fused_edge_kernel,
                         cudaFuncAttributeMaxDynamicSharedMemorySize, SMEM_BYTES);
    fused_edge_kernel<<<296, 256, SMEM_BYTES>>>(node_emb,
                                                W1, b1, W2, b2, Wg, bg, out, E);

    norm_kernel<<<(N * DD + 255) / 256, 256>>>(out, N * DD);
}

// round 13
// speedup vs baseline: 1.7238x; 1.3374x over previous
#include <cuda_runtime.h>
#include <cstdint>

#define DD 64
#define WARPS 8
#define EPT 32                  // edges per warp tile
#define TILE_E (WARPS * EPT)    // 256 edges per block-tile
#define SA_STRIDE 132           // pair/h/t row stride (conflict-free: bank=4r+c)
#define SW2_STRIDE 68

// smem float offsets
#define W1_OFF 0                                   // W1^T [64 n][132]
#define W2_OFF 8448                                // W2^T [64 n][68]
#define WG_OFF 12800                               // Wg^T [64 n][68]
#define B_OFF  17152                               // b1,b2,bg (3*64)
#define A_OFF  17344                               // per-warp [32][132]
#define SMEM_FLOATS (A_OFF + WARPS * EPT * SA_STRIDE)
#define SMEM_BYTES (SMEM_FLOATS * 4)               // 204544 B

#define MAXE (1 << 20)
#define MAXN 65536

__device__ int g_cnt[MAXN];
__device__ int g_src[MAXE];
__device__ int g_dst[MAXE];
__device__ int g_is64;

__device__ __forceinline__ void mma_tf32(float* d, const unsigned* a, const unsigned* b) {
    asm volatile(
        "mma.sync.aligned.m16n8k8.row.col.f32.tf32.tf32.f32 "
        "{%0,%1,%2,%3}, {%4,%5,%6,%7}, {%8,%9}, {%0,%1,%2,%3};"
        : "+f"(d[0]), "+f"(d[1]), "+f"(d[2]), "+f"(d[3])
        : "r"(a[0]), "r"(a[1]), "r"(a[2]), "r"(a[3]), "r"(b[0]), "r"(b[1]));
}
// split x into tf32-exact hi + fp32 residual lo (exact: a = hi + lo)
__device__ __forceinline__ void tf32_split(float x, unsigned& hi, unsigned& lo) {
    asm("cvt.rna.tf32.f32 %0, %1;" : "=r"(hi) : "f"(x));
    lo = __float_as_uint(x - __uint_as_float(hi));
}
__device__ __forceinline__ void red_v2(float* p, float a, float b) {
    asm volatile("red.global.add.v2.f32 [%0], {%1,%2};"
                 :: "l"(p), "f"(a), "f"(b) : "memory");
}
__device__ __forceinline__ float sigmoidf(float x) {
    return __fdividef(1.0f, 1.0f + __expf(-x));
}

__global__ void zero_kernel(float* __restrict__ out, int n_out, int n_cnt) {
    int stride = gridDim.x * blockDim.x;
    int i = blockIdx.x * blockDim.x + threadIdx.x;
    for (int j = i; j < n_out; j += stride) out[j] = 0.0f;
    for (int j = i; j < n_cnt; j += stride) g_cnt[j] = 0;
}

// int64 vs int32 detection: int64 nonneg values -> all odd int32 words zero.
__global__ void detect_kernel(const int* __restrict__ w) {
    if (threadIdx.x == 0) {
        int all_zero = 1;
        for (int i = 0; i < 64; i++)
            if (w[2 * i + 1] != 0) { all_zero = 0; break; }
        g_is64 = all_zero;
    }
}

__global__ void decode_kernel(const void* __restrict__ buf, int E, int N) {
    int i = blockIdx.x * blockDim.x + threadIdx.x;
    if (i >= E) return;
    int s, d;
    if (g_is64) {
        const long long* p = (const long long*)buf;
        s = (int)p[i]; d = (int)p[E + i];
    } else {
        const int* p = (const int*)buf;
        s = p[i]; d = p[E + i];
    }
    s = min(max(s, 0), N - 1);
    d = min(max(d, 0), N - 1);
    g_src[i] = s;
    g_dst[i] = d;
    atomicAdd(&g_cnt[s], 1);
}

__global__ __launch_bounds__(256, 1) void mma_edge_kernel(
    const float* __restrict__ node_emb,
    const float* __restrict__ W1, const float* __restrict__ b1,
    const float* __restrict__ W2, const float* __restrict__ b2,
    const float* __restrict__ Wg, const float* __restrict__ bg,
    float* __restrict__ out, int E)
{
    extern __shared__ float smem[];
    const int tid = threadIdx.x, wid = tid >> 5, lane = tid & 31;
    const int eq = lane >> 2;     // quad (row group)
    const int qt = lane & 3;      // thread in quad

    // ---- stage transposed weights + biases (once per CTA) ----
    for (int i = tid; i < 64 * 128; i += 256) {
        int n = i >> 7, k = i & 127;
        smem[W1_OFF + n * SA_STRIDE + k] = W1[k * 64 + n];
    }
    for (int i = tid; i < 64 * 64; i += 256) {
        int n = i >> 6, k = i & 63;
        smem[W2_OFF + n * SW2_STRIDE + k] = W2[k * 64 + n];
        smem[WG_OFF + n * SW2_STRIDE + k] = Wg[k * 64 + n];
    }
    for (int i = tid; i < 64; i += 256) {
        smem[B_OFF + i] = b1[i];
        smem[B_OFF + 64 + i] = b2[i];
        smem[B_OFF + 128 + i] = bg[i];
    }
    __syncthreads();

    float* sA = smem + A_OFF + wid * (EPT * SA_STRIDE);

    const int ntiles = (E + TILE_E - 1) / TILE_E;
    for (int tile = blockIdx.x; tile < ntiles; tile += gridDim.x) {
        const int base = tile * TILE_E + wid * EPT;
        if (base >= E) continue;

        // ---- gather pair embeddings: lanes 0-15 src half, 16-31 dst ----
        {
            const int half = (lane < 16) ? 0 : 64;
            const int j = lane & 15;
            #pragma unroll 4
            for (int i = 0; i < EPT; i++) {
                int ei = min(base + i, E - 1);
                int node = (lane < 16) ? g_src[ei] : g_dst[ei];
                float4 v = *(const float4*)(node_emb + (size_t)node * DD + j * 4);
                *(float4*)(sA + i * SA_STRIDE + half + j * 4) = v;
            }
        }
        __syncwarp();

        // ---- GEMM1: D1[32x64] = pair[32x128] @ W1t  (16 k-steps, 3xTF32) ----
        float D1[2][8][4];
        #pragma unroll
        for (int mt = 0; mt < 2; mt++)
            #pragma unroll
            for (int nb = 0; nb < 8; nb++)
                D1[mt][nb][0] = D1[mt][nb][1] = D1[mt][nb][2] = D1[mt][nb][3] = 0.0f;
        #pragma unroll 2
        for (int ks = 0; ks < 16; ks++) {
            unsigned bh[8][2], bl[8][2], ah[2][4], al[2][4];
            #pragma unroll
            for (int nb = 0; nb < 8; nb++) {
                const float* wp = smem + W1_OFF + (nb * 8 + eq) * SA_STRIDE + ks * 8 + qt;
                tf32_split(wp[0], bh[nb][0], bl[nb][0]);
                tf32_split(wp[4], bh[nb][1], bl[nb][1]);
            }
            #pragma unroll
            for (int mt = 0; mt < 2; mt++) {
                const float* ap = sA + (mt * 16 + eq) * SA_STRIDE + ks * 8 + qt;
                tf32_split(ap[0],                  ah[mt][0], al[mt][0]);
                tf32_split(ap[8 * SA_STRIDE],      ah[mt][1], al[mt][1]);
                tf32_split(ap[4],                  ah[mt][2], al[mt][2]);
                tf32_split(ap[8 * SA_STRIDE + 4],  ah[mt][3], al[mt][3]);
            }
            #pragma unroll
            for (int mt = 0; mt < 2; mt++)
                #pragma unroll
                for (int nb = 0; nb < 8; nb++) {
                    mma_tf32(D1[mt][nb], ah[mt], bh[nb]);
                    mma_tf32(D1[mt][nb], ah[mt], bl[nb]);
                    mma_tf32(D1[mt][nb], al[mt], bh[nb]);
                }
        }
        __syncwarp();

        // ---- epilogue 1: h = relu(D1 + b1) -> sA cols 0..63 ----
        #pragma unroll
        for (int mt = 0; mt < 2; mt++) {
            int r0 = mt * 16 + eq;
            #pragma unroll
            for (int nb = 0; nb < 8; nb++) {
                int c = nb * 8 + 2 * qt;
                float bb0 = smem[B_OFF + c], bb1 = smem[B_OFF + c + 1];
                float2 h0 = make_float2(fmaxf(D1[mt][nb][0] + bb0, 0.0f),
                                        fmaxf(D1[mt][nb][1] + bb1, 0.0f));
                float2 h1 = make_float2(fmaxf(D1[mt][nb][2] + bb0, 0.0f),
                                        fmaxf(D1[mt][nb][3] + bb1, 0.0f));
                *(float2*)(sA + r0 * SA_STRIDE + c) = h0;
                *(float2*)(sA + (r0 + 8) * SA_STRIDE + c) = h1;
            }
        }
        __syncwarp();

        // ---- GEMM2: D2 = h @ W2t  (8 k-steps, 3xTF32) ----
        float D2[2][8][4];
        #pragma unroll
        for (int mt = 0; mt < 2; mt++)
            #pragma unroll
            for (int nb = 0; nb < 8; nb++)
                D2[mt][nb][0] = D2[mt][nb][1] = D2[mt][nb][2] = D2[mt][nb][3] = 0.0f;
        #pragma unroll 2
        for (int ks = 0; ks < 8; ks++) {
            unsigned bh[8][2], bl[8][2], ah[2][4], al[2][4];
            #pragma unroll
            for (int nb = 0; nb < 8; nb++) {
                const float* wp = smem + W2_OFF + (nb * 8 + eq) * SW2_STRIDE + ks * 8 + qt;
                tf32_split(wp[0], bh[nb][0], bl[nb][0]);
                tf32_split(wp[4], bh[nb][1], bl[nb][1]);
            }
            #pragma unroll
            for (int mt = 0; mt < 2; mt++) {
                const float* ap = sA + (mt * 16 + eq) * SA_STRIDE + ks * 8 + qt;
                tf32_split(ap[0],                  ah[mt][0], al[mt][0]);
                tf32_split(ap[8 * SA_STRIDE],      ah[mt][1], al[mt][1]);
                tf32_split(ap[4],                  ah[mt][2], al[mt][2]);
                tf32_split(ap[8 * SA_STRIDE + 4],  ah[mt][3], al[mt][3]);
            }
            #pragma unroll
            for (int mt = 0; mt < 2; mt++)
                #pragma unroll
                for (int nb = 0; nb < 8; nb++) {
                    mma_tf32(D2[mt][nb], ah[mt], bh[nb]);
                    mma_tf32(D2[mt][nb], ah[mt], bl[nb]);
                    mma_tf32(D2[mt][nb], al[mt], bh[nb]);
                }
        }
        __syncwarp();

        // ---- epilogue 2: t = D2 + b2 -> sA cols 64..127 ----
        #pragma unroll
        for (int mt = 0; mt < 2; mt++) {
            int r0 = mt * 16 + eq;
            #pragma unroll
            for (int nb = 0; nb < 8; nb++) {
                int c = nb * 8 + 2 * qt;
                float bb0 = smem[B_OFF + 64 + c], bb1 = smem[B_OFF + 64 + c + 1];
                float2 t0 = make_float2(D2[mt][nb][0] + bb0, D2[mt][nb][1] + bb1);
                float2 t1 = make_float2(D2[mt][nb][2] + bb0, D2[mt][nb][3] + bb1);
                *(float2*)(sA + r0 * SA_STRIDE + 64 + c) = t0;
                *(float2*)(sA + (r0 + 8) * SA_STRIDE + 64 + c) = t1;
            }
        }
        __syncwarp();

        // ---- GEMM3: D3 = t @ Wgt  (8 k-steps, 3xTF32) ----
        float D3[2][8][4];
        #pragma unroll
        for (int mt = 0; mt < 2; mt++)
            #pragma unroll
            for (int nb = 0; nb < 8; nb++)
                D3[mt][nb][0] = D3[mt][nb][1] = D3[mt][nb][2] = D3[mt][nb][3] = 0.0f;
        #pragma unroll 2
        for (int ks = 0; ks < 8; ks++) {
            unsigned bh[8][2], bl[8][2], ah[2][4], al[2][4];
            #pragma unroll
            for (int nb = 0; nb < 8; nb++) {
                const float* wp = smem + WG_OFF + (nb * 8 + eq) * SW2_STRIDE + ks * 8 + qt;
                tf32_split(wp[0], bh[nb][0], bl[nb][0]);
                tf32_split(wp[4], bh[nb][1], bl[nb][1]);
            }
            #pragma unroll
            for (int mt = 0; mt < 2; mt++) {
                const float* ap = sA + (mt * 16 + eq) * SA_STRIDE + 64 + ks * 8 + qt;
                tf32_split(ap[0],                  ah[mt][0], al[mt][0]);
                tf32_split(ap[8 * SA_STRIDE],      ah[mt][1], al[mt][1]);
                tf32_split(ap[4],                  ah[mt][2], al[mt][2]);
                tf32_split(ap[8 * SA_STRIDE + 4],  ah[mt][3], al[mt][3]);
            }
            #pragma unroll
            for (int mt = 0; mt < 2; mt++)
                #pragma unroll
                for (int nb = 0; nb < 8; nb++) {
                    mma_tf32(D3[mt][nb], ah[mt], bh[nb]);
                    mma_tf32(D3[mt][nb], ah[mt], bl[nb]);
                    mma_tf32(D3[mt][nb], al[mt], bh[nb]);
                }
        }

        // ---- epilogue 3: gated = t * sigmoid(D3 + bg); scatter-add to src rows ----
        #pragma unroll
        for (int mt = 0; mt < 2; mt++) {
            int r0 = mt * 16 + eq;
            int e0 = base + r0, e1 = base + r0 + 8;
            bool v0 = e0 < E, v1 = e1 < E;
            int s0 = g_src[min(e0, E - 1)];
            int s1 = g_src[min(e1, E - 1)];
            #pragma unroll
            for (int nb = 0; nb < 8; nb++) {
                int c = nb * 8 + 2 * qt;
                float bg0 = smem[B_OFF + 128 + c], bg1 = smem[B_OFF + 128 + c + 1];
                float2 t0 = *(const float2*)(sA + r0 * SA_STRIDE + 64 + c);
                float2 t1 = *(const float2*)(sA + (r0 + 8) * SA_STRIDE + 64 + c);
                if (v0) {
                    float ga = sigmoidf(D3[mt][nb][0] + bg0);
                    float gb = sigmoidf(D3[mt][nb][1] + bg1);
                    red_v2(out + (size_t)s0 * DD + c, t0.x * ga, t0.y * gb);
                }
                if (v1) {
                    float ga = sigmoidf(D3[mt][nb][2] + bg0);
                    float gb = sigmoidf(D3[mt][nb][3] + bg1);
                    red_v2(out + (size_t)s1 * DD + c, t1.x * ga, t1.y * gb);
                }
            }
        }
        __syncwarp();   // sA reuse safety before next tile's gather
    }
}

__global__ void norm_kernel(float* __restrict__ out, int n_out) {
    int i = blockIdx.x * blockDim.x + threadIdx.x;
    if (i < n_out) {
        float c = (float)g_cnt[i >> 6];
        out[i] = out[i] / fmaxf(c, 1.0f);
    }
}

extern "C" void kernel_launch(void* const* d_in, const int* in_sizes, int n_in,
                              void* d_out, int out_size)
{
    const float* node_emb = (const float*)d_in[0];
    const void*  ei       = d_in[1];
    const float* W1       = (const float*)d_in[2];
    const float* b1       = (const float*)d_in[3];
    const float* W2       = (const float*)d_in[4];
    const float* b2       = (const float*)d_in[5];
    const float* Wg       = (const float*)d_in[6];
    const float* bg       = (const float*)d_in[7];
    float*       out      = (float*)d_out;

    const int N = in_sizes[0] / DD;
    const int E = in_sizes[1] / 2;

    zero_kernel<<<256, 256>>>(out, N * DD, N);
    detect_kernel<<<1, 32>>>((const int*)ei);
    decode_kernel<<<(E + 255) / 256, 256>>>(ei, E, N);

    cudaFuncSetAttribute(mma_edge_kernel,
                         cudaFuncAttributeMaxDynamicSharedMemorySize, SMEM_BYTES);
    mma_edge_kernel<<<148, 256, SMEM_BYTES>>>(node_emb,
                                              W1, b1, W2, b2, Wg, bg, out, E);

    norm_kernel<<<(N * DD + 255) / 256, 256>>>(out, N * DD);
}

// round 14
// speedup vs baseline: 1.7661x; 1.0245x over previous
#include <cuda_runtime.h>
#include <cstdint>

#define DD 64
#define WARPS 16
#define EPT 16                  // edges per warp tile
#define TILE_E (WARPS * EPT)    // 256 edges per block-tile
#define SA_STRIDE 132           // pair/h/t row stride (conflict-free: bank=4r+c)
#define SW2_STRIDE 68
#define NTHREADS 512

// smem float offsets
#define W1_OFF 0                                   // W1^T [64 n][132]
#define W2_OFF 8448                                // W2^T [64 n][68]
#define WG_OFF 12800                               // Wg^T [64 n][68]
#define B_OFF  17152                               // b1,b2,bg (3*64)
#define A_OFF  17344                               // per-warp [16][132]
#define SMEM_FLOATS (A_OFF + WARPS * EPT * SA_STRIDE)
#define SMEM_BYTES (SMEM_FLOATS * 4)               // 204544 B

#define MAXE (1 << 20)
#define MAXN 65536

__device__ int g_cnt[MAXN];
__device__ int g_src[MAXE];
__device__ int g_dst[MAXE];
__device__ int g_is64;

__device__ __forceinline__ void mma_tf32(float* d, const unsigned* a, const unsigned* b) {
    asm volatile(
        "mma.sync.aligned.m16n8k8.row.col.f32.tf32.tf32.f32 "
        "{%0,%1,%2,%3}, {%4,%5,%6,%7}, {%8,%9}, {%0,%1,%2,%3};"
        : "+f"(d[0]), "+f"(d[1]), "+f"(d[2]), "+f"(d[3])
        : "r"(a[0]), "r"(a[1]), "r"(a[2]), "r"(a[3]), "r"(b[0]), "r"(b[1]));
}
// split x into tf32-exact hi + fp32 residual lo (exact: x = hi + lo)
__device__ __forceinline__ void tf32_split(float x, unsigned& hi, unsigned& lo) {
    asm("cvt.rna.tf32.f32 %0, %1;" : "=r"(hi) : "f"(x));
    lo = __float_as_uint(x - __uint_as_float(hi));
}
__device__ __forceinline__ void red_v2(float* p, float a, float b) {
    asm volatile("red.global.add.v2.f32 [%0], {%1,%2};"
                 :: "l"(p), "f"(a), "f"(b) : "memory");
}
__device__ __forceinline__ float sigmoidf(float x) {
    return __fdividef(1.0f, 1.0f + __expf(-x));
}

__global__ void zero_kernel(float* __restrict__ out, int n_out, int n_cnt) {
    int stride = gridDim.x * blockDim.x;
    int i = blockIdx.x * blockDim.x + threadIdx.x;
    for (int j = i; j < n_out; j += stride) out[j] = 0.0f;
    for (int j = i; j < n_cnt; j += stride) g_cnt[j] = 0;
}

// int64 vs int32 detection: int64 nonneg values -> all odd int32 words zero.
__global__ void detect_kernel(const int* __restrict__ w) {
    if (threadIdx.x == 0) {
        int all_zero = 1;
        for (int i = 0; i < 64; i++)
            if (w[2 * i + 1] != 0) { all_zero = 0; break; }
        g_is64 = all_zero;
    }
}

__global__ void decode_kernel(const void* __restrict__ buf, int E, int N) {
    int i = blockIdx.x * blockDim.x + threadIdx.x;
    if (i >= E) return;
    int s, d;
    if (g_is64) {
        const long long* p = (const long long*)buf;
        s = (int)p[i]; d = (int)p[E + i];
    } else {
        const int* p = (const int*)buf;
        s = p[i]; d = p[E + i];
    }
    s = min(max(s, 0), N - 1);
    d = min(max(d, 0), N - 1);
    g_src[i] = s;
    g_dst[i] = d;
    atomicAdd(&g_cnt[s], 1);
}

__global__ __launch_bounds__(NTHREADS, 1) void mma_edge_kernel(
    const float* __restrict__ node_emb,
    const float* __restrict__ W1, const float* __restrict__ b1,
    const float* __restrict__ W2, const float* __restrict__ b2,
    const float* __restrict__ Wg, const float* __restrict__ bg,
    float* __restrict__ out, int E)
{
    extern __shared__ float smem[];
    const int tid = threadIdx.x, wid = tid >> 5, lane = tid & 31;
    const int eq = lane >> 2;     // quad (row group)
    const int qt = lane & 3;      // thread in quad

    // ---- stage transposed weights + biases (once per CTA) ----
    for (int i = tid; i < 64 * 128; i += NTHREADS) {
        int n = i >> 7, k = i & 127;
        smem[W1_OFF + n * SA_STRIDE + k] = W1[k * 64 + n];
    }
    for (int i = tid; i < 64 * 64; i += NTHREADS) {
        int n = i >> 6, k = i & 63;
        smem[W2_OFF + n * SW2_STRIDE + k] = W2[k * 64 + n];
        smem[WG_OFF + n * SW2_STRIDE + k] = Wg[k * 64 + n];
    }
    for (int i = tid; i < 64; i += NTHREADS) {
        smem[B_OFF + i] = b1[i];
        smem[B_OFF + 64 + i] = b2[i];
        smem[B_OFF + 128 + i] = bg[i];
    }
    __syncthreads();

    float* sA = smem + A_OFF + wid * (EPT * SA_STRIDE);

    const int ntiles = (E + TILE_E - 1) / TILE_E;
    for (int tile = blockIdx.x; tile < ntiles; tile += gridDim.x) {
        const int base = tile * TILE_E + wid * EPT;
        if (base >= E) continue;

        // ---- gather pair embeddings: lanes 0-15 src half, 16-31 dst ----
        {
            const int half = (lane < 16) ? 0 : 64;
            const int j = lane & 15;
            #pragma unroll 4
            for (int i = 0; i < EPT; i++) {
                int ei = min(base + i, E - 1);
                int node = (lane < 16) ? g_src[ei] : g_dst[ei];
                float4 v = *(const float4*)(node_emb + (size_t)node * DD + j * 4);
                *(float4*)(sA + i * SA_STRIDE + half + j * 4) = v;
            }
        }
        __syncwarp();

        // ---- GEMM1: D1[16x64] = pair[16x128] @ W1t  (16 k-steps, 3xTF32) ----
        float D1[8][4];
        #pragma unroll
        for (int nb = 0; nb < 8; nb++)
            D1[nb][0] = D1[nb][1] = D1[nb][2] = D1[nb][3] = 0.0f;
        #pragma unroll 2
        for (int ks = 0; ks < 16; ks++) {
            unsigned bh[8][2], bl[8][2], ah[4], al[4];
            #pragma unroll
            for (int nb = 0; nb < 8; nb++) {
                const float* wp = smem + W1_OFF + (nb * 8 + eq) * SA_STRIDE + ks * 8 + qt;
                tf32_split(wp[0], bh[nb][0], bl[nb][0]);
                tf32_split(wp[4], bh[nb][1], bl[nb][1]);
            }
            {
                const float* ap = sA + eq * SA_STRIDE + ks * 8 + qt;
                tf32_split(ap[0],                 ah[0], al[0]);
                tf32_split(ap[8 * SA_STRIDE],     ah[1], al[1]);
                tf32_split(ap[4],                 ah[2], al[2]);
                tf32_split(ap[8 * SA_STRIDE + 4], ah[3], al[3]);
            }
            #pragma unroll
            for (int nb = 0; nb < 8; nb++) {
                mma_tf32(D1[nb], ah, bh[nb]);
                mma_tf32(D1[nb], ah, bl[nb]);
                mma_tf32(D1[nb], al, bh[nb]);
            }
        }
        __syncwarp();

        // ---- epilogue 1: h = relu(D1 + b1) -> sA cols 0..63 ----
        #pragma unroll
        for (int nb = 0; nb < 8; nb++) {
            int c = nb * 8 + 2 * qt;
            float bb0 = smem[B_OFF + c], bb1 = smem[B_OFF + c + 1];
            float2 h0 = make_float2(fmaxf(D1[nb][0] + bb0, 0.0f),
                                    fmaxf(D1[nb][1] + bb1, 0.0f));
            float2 h1 = make_float2(fmaxf(D1[nb][2] + bb0, 0.0f),
                                    fmaxf(D1[nb][3] + bb1, 0.0f));
            *(float2*)(sA + eq * SA_STRIDE + c) = h0;
            *(float2*)(sA + (eq + 8) * SA_STRIDE + c) = h1;
        }
        __syncwarp();

        // ---- GEMM2: D2 = h @ W2t  (8 k-steps, 3xTF32) ----
        float D2[8][4];
        #pragma unroll
        for (int nb = 0; nb < 8; nb++)
            D2[nb][0] = D2[nb][1] = D2[nb][2] = D2[nb][3] = 0.0f;
        #pragma unroll 2
        for (int ks = 0; ks < 8; ks++) {
            unsigned bh[8][2], bl[8][2], ah[4], al[4];
            #pragma unroll
            for (int nb = 0; nb < 8; nb++) {
                const float* wp = smem + W2_OFF + (nb * 8 + eq) * SW2_STRIDE + ks * 8 + qt;
                tf32_split(wp[0], bh[nb][0], bl[nb][0]);
                tf32_split(wp[4], bh[nb][1], bl[nb][1]);
            }
            {
                const float* ap = sA + eq * SA_STRIDE + ks * 8 + qt;
                tf32_split(ap[0],                 ah[0], al[0]);
                tf32_split(ap[8 * SA_STRIDE],     ah[1], al[1]);
                tf32_split(ap[4],                 ah[2], al[2]);
                tf32_split(ap[8 * SA_STRIDE + 4], ah[3], al[3]);
            }
            #pragma unroll
            for (int nb = 0; nb < 8; nb++) {
                mma_tf32(D2[nb], ah, bh[nb]);
                mma_tf32(D2[nb], ah, bl[nb]);
                mma_tf32(D2[nb], al, bh[nb]);
            }
        }
        __syncwarp();

        // ---- epilogue 2: t = D2 + b2 -> sA cols 64..127 ----
        #pragma unroll
        for (int nb = 0; nb < 8; nb++) {
            int c = nb * 8 + 2 * qt;
            float bb0 = smem[B_OFF + 64 + c], bb1 = smem[B_OFF + 64 + c + 1];
            float2 t0 = make_float2(D2[nb][0] + bb0, D2[nb][1] + bb1);
            float2 t1 = make_float2(D2[nb][2] + bb0, D2[nb][3] + bb1);
            *(float2*)(sA + eq * SA_STRIDE + 64 + c) = t0;
            *(float2*)(sA + (eq + 8) * SA_STRIDE + 64 + c) = t1;
        }
        __syncwarp();

        // ---- GEMM3: D3 = t @ Wgt  (8 k-steps, 3xTF32) ----
        float D3[8][4];
        #pragma unroll
        for (int nb = 0; nb < 8; nb++)
            D3[nb][0] = D3[nb][1] = D3[nb][2] = D3[nb][3] = 0.0f;
        #pragma unroll 2
        for (int ks = 0; ks < 8; ks++) {
            unsigned bh[8][2], bl[8][2], ah[4], al[4];
            #pragma unroll
            for (int nb = 0; nb < 8; nb++) {
                const float* wp = smem + WG_OFF + (nb * 8 + eq) * SW2_STRIDE + ks * 8 + qt;
                tf32_split(wp[0], bh[nb][0], bl[nb][0]);
                tf32_split(wp[4], bh[nb][1], bl[nb][1]);
            }
            {
                const float* ap = sA + eq * SA_STRIDE + 64 + ks * 8 + qt;
                tf32_split(ap[0],                 ah[0], al[0]);
                tf32_split(ap[8 * SA_STRIDE],     ah[1], al[1]);
                tf32_split(ap[4],                 ah[2], al[2]);
                tf32_split(ap[8 * SA_STRIDE + 4], ah[3], al[3]);
            }
            #pragma unroll
            for (int nb = 0; nb < 8; nb++) {
                mma_tf32(D3[nb], ah, bh[nb]);
                mma_tf32(D3[nb], ah, bl[nb]);
                mma_tf32(D3[nb], al, bh[nb]);
            }
        }

        // ---- epilogue 3: gated = t * sigmoid(D3 + bg); scatter-add to src rows ----
        {
            int e0 = base + eq, e1 = base + eq + 8;
            bool v0 = e0 < E, v1 = e1 < E;
            int s0 = g_src[min(e0, E - 1)];
            int s1 = g_src[min(e1, E - 1)];
            #pragma unroll
            for (int nb = 0; nb < 8; nb++) {
                int c = nb * 8 + 2 * qt;
                float bg0 = smem[B_OFF + 128 + c], bg1 = smem[B_OFF + 128 + c + 1];
                float2 t0 = *(const float2*)(sA + eq * SA_STRIDE + 64 + c);
                float2 t1 = *(const float2*)(sA + (eq + 8) * SA_STRIDE + 64 + c);
                if (v0) {
                    float ga = sigmoidf(D3[nb][0] + bg0);
                    float gb = sigmoidf(D3[nb][1] + bg1);
                    red_v2(out + (size_t)s0 * DD + c, t0.x * ga, t0.y * gb);
                }
                if (v1) {
                    float ga = sigmoidf(D3[nb][2] + bg0);
                    float gb = sigmoidf(D3[nb][3] + bg1);
                    red_v2(out + (size_t)s1 * DD + c, t1.x * ga, t1.y * gb);
                }
            }
        }
        __syncwarp();   // sA reuse safety before next tile's gather
    }
}

__global__ void norm_kernel(float* __restrict__ out, int n_out) {
    int i = blockIdx.x * blockDim.x + threadIdx.x;
    if (i < n_out) {
        float c = (float)g_cnt[i >> 6];
        out[i] = out[i] / fmaxf(c, 1.0f);
    }
}

extern "C" void kernel_launch(void* const* d_in, const int* in_sizes, int n_in,
                              void* d_out, int out_size)
{
    const float* node_emb = (const float*)d_in[0];
    const void*  ei       = d_in[1];
    const float* W1       = (const float*)d_in[2];
    const float* b1       = (const float*)d_in[3];
    const float* W2       = (const float*)d_in[4];
    const float* b2       = (const float*)d_in[5];
    const float* Wg       = (const float*)d_in[6];
    const float* bg       = (const float*)d_in[7];
    float*       out      = (float*)d_out;

    const int N = in_sizes[0] / DD;
    const int E = in_sizes[1] / 2;

    zero_kernel<<<256, 256>>>(out, N * DD, N);
    detect_kernel<<<1, 32>>>((const int*)ei);
    decode_kernel<<<(E + 255) / 256, 256>>>(ei, E, N);

    cudaFuncSetAttribute(mma_edge_kernel,
                         cudaFuncAttributeMaxDynamicSharedMemorySize, SMEM_BYTES);
    mma_edge_kernel<<<148, NTHREADS, SMEM_BYTES>>>(node_emb,
                                                   W1, b1, W2, b2, Wg, bg, out, E);

    norm_kernel<<<(N * DD + 255) / 256, 256>>>(out, N * DD);
}